// round 7
// baseline (speedup 1.0000x reference)
#include <cuda_runtime.h>

// SpatialTransformer3D: B=4, vol 128^3, C=2, resampled 128^3.
// R7 = R4 champion, instruction-stripped:
//  - transform params in __constant__ (uniform LDC, no L1 wavefronts)
//  - single float2 smem plane (STS.64/LDS.64 at the 2-phase floor)
//  - 1-fmaf-per-axis incremental coordinates
//  - 3D grid decode
// Tile 32(i1) x 32(i2); lanes along i1 for coalesced gathers, smem transpose
// for coalesced stores along i2. 2 i2-steps batched per loop body (16 loads
// in flight).

#define R3_ (128*128*128)

__constant__ float c_params[48];   // B=4 x 12

__device__ __forceinline__ int clampi(int v, int lo, int hi) {
    return v < lo ? lo : (v > hi ? hi : v);
}

struct Corner {
    int x0, x1;
    int r00, r01, r10, r11;   // (z<<14)+(y<<7) combos, float2 units
    float wx0, wx1, wy0, wy1, wz0, wz1;
};

__device__ __forceinline__ Corner make_corner(float x, float y, float z) {
    Corner c;
    int xi = (int)x, yi = (int)y, zi = (int)z;   // trunc toward zero (astype)
    c.x0 = clampi(xi,     0, 127);
    c.x1 = clampi(xi + 1, 0, 127);
    int y0 = clampi(yi,     0, 127);
    int y1 = clampi(yi + 1, 0, 127);
    int z0 = clampi(zi,     0, 127);
    int z1 = clampi(zi + 1, 0, 127);
    c.wx0 = (float)c.x1 - x;  c.wx1 = x - (float)c.x0;
    c.wy0 = (float)y1   - y;  c.wy1 = y - (float)y0;
    c.wz0 = (float)z1   - z;  c.wz1 = z - (float)z0;
    int iz0 = z0 << 14, iz1 = z1 << 14;
    int iy0 = y0 << 7,  iy1 = y1 << 7;
    c.r00 = iz0 + iy0;  c.r01 = iz0 + iy1;
    c.r10 = iz1 + iy0;  c.r11 = iz1 + iy1;
    return c;
}

__device__ __forceinline__ float2 lerp8(const Corner& c,
    float2 v000, float2 v001, float2 v010, float2 v011,
    float2 v100, float2 v101, float2 v110, float2 v111)
{
    float wxy00 = c.wx0 * c.wy0;
    float wxy01 = c.wx0 * c.wy1;
    float wxy10 = c.wx1 * c.wy0;
    float wxy11 = c.wx1 * c.wy1;
    float w000 = wxy00 * c.wz0, w100 = wxy00 * c.wz1;
    float w010 = wxy01 * c.wz0, w110 = wxy01 * c.wz1;
    float w001 = wxy10 * c.wz0, w101 = wxy10 * c.wz1;
    float w011 = wxy11 * c.wz0, w111 = wxy11 * c.wz1;

    float2 acc;
    acc.x = w000 * v000.x;                 acc.y = w000 * v000.y;
    acc.x = fmaf(w100, v100.x, acc.x);     acc.y = fmaf(w100, v100.y, acc.y);
    acc.x = fmaf(w010, v010.x, acc.x);     acc.y = fmaf(w010, v010.y, acc.y);
    acc.x = fmaf(w110, v110.x, acc.x);     acc.y = fmaf(w110, v110.y, acc.y);
    acc.x = fmaf(w001, v001.x, acc.x);     acc.y = fmaf(w001, v001.y, acc.y);
    acc.x = fmaf(w101, v101.x, acc.x);     acc.y = fmaf(w101, v101.y, acc.y);
    acc.x = fmaf(w011, v011.x, acc.x);     acc.y = fmaf(w011, v011.y, acc.y);
    acc.x = fmaf(w111, v111.x, acc.x);     acc.y = fmaf(w111, v111.y, acc.y);
    return acc;
}

__global__ __launch_bounds__(256, 4)
void st3d_kernel(const float* __restrict__ images,
                 float2* __restrict__ out)
{
    __shared__ float2 tile[32][33];

    int lane = threadIdx.x & 31;
    int warp = threadIdx.x >> 5;

    int i2t = (blockIdx.x & 3) << 5;
    int i1t = (blockIdx.x >> 2) << 5;
    int i0  = blockIdx.y;
    int b   = blockIdx.z;

    const float* m = c_params + b * 12;   // uniform -> LDC, no L1 traffic
    float m00 = m[0],  m01 = m[1],  m02 = m[2],  m03 = m[3];
    float m10 = m[4],  m11 = m[5],  m12 = m[6],  m13 = m[7];
    float m20 = m[8],  m21 = m[9],  m22 = m[10], m23 = m[11];

    const float step = 2.0f / 127.0f;
    int i1 = i1t + lane;
    float xn = fmaf((float)i1, step, -1.0f);
    float yn = fmaf((float)i0, step, -1.0f);

    // coord(fi2) = d * fi2 + c
    float gx = fmaf(m00, xn, fmaf(m01, yn, m03));
    float gy = fmaf(m10, xn, fmaf(m11, yn, m13));
    float gz = fmaf(m20, xn, fmaf(m21, yn, m23));
    float dxz = 64.0f * step * m02;
    float dyz = 64.0f * step * m12;
    float dzz = 64.0f * step * m22;
    float cx = (gx - m02 + 1.0f) * 64.0f;
    float cy = (gy - m12 + 1.0f) * 64.0f;
    float cz = (gz - m22 + 1.0f) * 64.0f;

    const float2* __restrict__ vol = (const float2*)images + (size_t)b * R3_;

    float fbase = (float)(i2t + (warp << 2));

    #pragma unroll
    for (int jj = 0; jj < 2; jj++) {
        float fA = fbase + (float)(jj * 2);
        float fB = fA + 1.0f;

        Corner A = make_corner(fmaf(dxz, fA, cx), fmaf(dyz, fA, cy), fmaf(dzz, fA, cz));
        Corner B = make_corner(fmaf(dxz, fB, cx), fmaf(dyz, fB, cy), fmaf(dzz, fB, cz));

        // all 16 gathers issued before any consumption (max MLP)
        float2 a000 = __ldg(vol + A.r00 + A.x0);
        float2 a100 = __ldg(vol + A.r10 + A.x0);
        float2 a010 = __ldg(vol + A.r01 + A.x0);
        float2 a110 = __ldg(vol + A.r11 + A.x0);
        float2 a001 = __ldg(vol + A.r00 + A.x1);
        float2 a101 = __ldg(vol + A.r10 + A.x1);
        float2 a011 = __ldg(vol + A.r01 + A.x1);
        float2 a111 = __ldg(vol + A.r11 + A.x1);

        float2 b000 = __ldg(vol + B.r00 + B.x0);
        float2 b100 = __ldg(vol + B.r10 + B.x0);
        float2 b010 = __ldg(vol + B.r01 + B.x0);
        float2 b110 = __ldg(vol + B.r11 + B.x0);
        float2 b001 = __ldg(vol + B.r00 + B.x1);
        float2 b101 = __ldg(vol + B.r10 + B.x1);
        float2 b011 = __ldg(vol + B.r01 + B.x1);
        float2 b111 = __ldg(vol + B.r11 + B.x1);

        int rowA = (warp << 2) + jj * 2;
        tile[rowA][lane] =
            lerp8(A, a000, a001, a010, a011, a100, a101, a110, a111);
        tile[rowA + 1][lane] =
            lerp8(B, b000, b001, b010, b011, b100, b101, b110, b111);
    }

    __syncthreads();

    size_t out_base = (((size_t)b << 7) + i0) << 14;
    #pragma unroll
    for (int j = 0; j < 4; j++) {
        int i1l = warp + (j << 3);
        float2 v = tile[lane][i1l];
        out[out_base + (size_t)(i1t + i1l) * 128 + (i2t + lane)] = v;
    }
}

extern "C" void kernel_launch(void* const* d_in, const int* in_sizes, int n_in,
                              void* d_out, int out_size)
{
    const float* images = (const float*)d_in[0];
    const float* params = (const float*)d_in[1];
    float2* out = (float2*)d_out;

    cudaMemcpyToSymbolAsync(c_params, params, 48 * sizeof(float), 0,
                            cudaMemcpyDeviceToDevice, 0);

    dim3 grid(16, 128, 4);   // (i2t,i1t) x i0 x b
    st3d_kernel<<<grid, 256>>>(images, out);
}

// round 8
// speedup vs baseline: 1.0348x; 1.0348x over previous
#include <cuda_runtime.h>

// SpatialTransformer3D: B=4, vol 128^3, C=2, resampled 128^3.
// R8 = all validated wins stacked:
//  - 32(i1) x 32(i2) tile; lanes along i1 (coalesced gathers)
//  - 16 loads in flight (2 i2-steps batched)
//  - conflict-free SPLIT float planes for the transpose (bank = lane+col)
//  - 1-fmaf-per-axis incremental coordinates
//  - 3D grid decode, params via __ldg (single graph node)

#define R3_ (128*128*128)

__device__ __forceinline__ int clampi(int v, int lo, int hi) {
    return v < lo ? lo : (v > hi ? hi : v);
}

struct Corner {
    int x0, x1;
    int r00, r01, r10, r11;   // (z<<14)+(y<<7) combos, float2 units
    float wx0, wx1, wy0, wy1, wz0, wz1;
};

__device__ __forceinline__ Corner make_corner(float x, float y, float z) {
    Corner c;
    int xi = (int)x, yi = (int)y, zi = (int)z;   // trunc toward zero (astype)
    c.x0 = clampi(xi,     0, 127);
    c.x1 = clampi(xi + 1, 0, 127);
    int y0 = clampi(yi,     0, 127);
    int y1 = clampi(yi + 1, 0, 127);
    int z0 = clampi(zi,     0, 127);
    int z1 = clampi(zi + 1, 0, 127);
    c.wx0 = (float)c.x1 - x;  c.wx1 = x - (float)c.x0;
    c.wy0 = (float)y1   - y;  c.wy1 = y - (float)y0;
    c.wz0 = (float)z1   - z;  c.wz1 = z - (float)z0;
    int iz0 = z0 << 14, iz1 = z1 << 14;
    int iy0 = y0 << 7,  iy1 = y1 << 7;
    c.r00 = iz0 + iy0;  c.r01 = iz0 + iy1;
    c.r10 = iz1 + iy0;  c.r11 = iz1 + iy1;
    return c;
}

__device__ __forceinline__ float2 lerp8(const Corner& c,
    float2 v000, float2 v001, float2 v010, float2 v011,
    float2 v100, float2 v101, float2 v110, float2 v111)
{
    float wxy00 = c.wx0 * c.wy0;
    float wxy01 = c.wx0 * c.wy1;
    float wxy10 = c.wx1 * c.wy0;
    float wxy11 = c.wx1 * c.wy1;
    float w000 = wxy00 * c.wz0, w100 = wxy00 * c.wz1;
    float w010 = wxy01 * c.wz0, w110 = wxy01 * c.wz1;
    float w001 = wxy10 * c.wz0, w101 = wxy10 * c.wz1;
    float w011 = wxy11 * c.wz0, w111 = wxy11 * c.wz1;

    float2 acc;
    acc.x = w000 * v000.x;                 acc.y = w000 * v000.y;
    acc.x = fmaf(w100, v100.x, acc.x);     acc.y = fmaf(w100, v100.y, acc.y);
    acc.x = fmaf(w010, v010.x, acc.x);     acc.y = fmaf(w010, v010.y, acc.y);
    acc.x = fmaf(w110, v110.x, acc.x);     acc.y = fmaf(w110, v110.y, acc.y);
    acc.x = fmaf(w001, v001.x, acc.x);     acc.y = fmaf(w001, v001.y, acc.y);
    acc.x = fmaf(w101, v101.x, acc.x);     acc.y = fmaf(w101, v101.y, acc.y);
    acc.x = fmaf(w011, v011.x, acc.x);     acc.y = fmaf(w011, v011.y, acc.y);
    acc.x = fmaf(w111, v111.x, acc.x);     acc.y = fmaf(w111, v111.y, acc.y);
    return acc;
}

__global__ __launch_bounds__(256, 4)
void st3d_kernel(const float* __restrict__ images,
                 const float* __restrict__ params,
                 float2* __restrict__ out)
{
    __shared__ float tx[32][33];   // conflict-free split planes:
    __shared__ float ty[32][33];   // bank = (row + lane) % 32 on both phases

    int lane = threadIdx.x & 31;
    int warp = threadIdx.x >> 5;

    int i2t = (blockIdx.x & 3) << 5;
    int i1t = (blockIdx.x >> 2) << 5;
    int i0  = blockIdx.y;
    int b   = blockIdx.z;

    const float* m = params + b * 12;
    float m00 = __ldg(m+0),  m01 = __ldg(m+1),  m02 = __ldg(m+2),  m03 = __ldg(m+3);
    float m10 = __ldg(m+4),  m11 = __ldg(m+5),  m12 = __ldg(m+6),  m13 = __ldg(m+7);
    float m20 = __ldg(m+8),  m21 = __ldg(m+9),  m22 = __ldg(m+10), m23 = __ldg(m+11);

    const float step = 2.0f / 127.0f;
    int i1 = i1t + lane;
    float xn = fmaf((float)i1, step, -1.0f);
    float yn = fmaf((float)i0, step, -1.0f);

    // coord(fi2) = d * fi2 + c
    float gx = fmaf(m00, xn, fmaf(m01, yn, m03));
    float gy = fmaf(m10, xn, fmaf(m11, yn, m13));
    float gz = fmaf(m20, xn, fmaf(m21, yn, m23));
    float dxz = 64.0f * step * m02;
    float dyz = 64.0f * step * m12;
    float dzz = 64.0f * step * m22;
    float cx = (gx - m02 + 1.0f) * 64.0f;
    float cy = (gy - m12 + 1.0f) * 64.0f;
    float cz = (gz - m22 + 1.0f) * 64.0f;

    const float2* __restrict__ vol = (const float2*)images + (size_t)b * R3_;

    float fbase = (float)(i2t + (warp << 2));

    #pragma unroll
    for (int jj = 0; jj < 2; jj++) {
        float fA = fbase + (float)(jj * 2);
        float fB = fA + 1.0f;

        Corner A = make_corner(fmaf(dxz, fA, cx), fmaf(dyz, fA, cy), fmaf(dzz, fA, cz));
        Corner B = make_corner(fmaf(dxz, fB, cx), fmaf(dyz, fB, cy), fmaf(dzz, fB, cz));

        // all 16 gathers issued before any consumption (max MLP)
        float2 a000 = __ldg(vol + A.r00 + A.x0);
        float2 a100 = __ldg(vol + A.r10 + A.x0);
        float2 a010 = __ldg(vol + A.r01 + A.x0);
        float2 a110 = __ldg(vol + A.r11 + A.x0);
        float2 a001 = __ldg(vol + A.r00 + A.x1);
        float2 a101 = __ldg(vol + A.r10 + A.x1);
        float2 a011 = __ldg(vol + A.r01 + A.x1);
        float2 a111 = __ldg(vol + A.r11 + A.x1);

        float2 b000 = __ldg(vol + B.r00 + B.x0);
        float2 b100 = __ldg(vol + B.r10 + B.x0);
        float2 b010 = __ldg(vol + B.r01 + B.x0);
        float2 b110 = __ldg(vol + B.r11 + B.x0);
        float2 b001 = __ldg(vol + B.r00 + B.x1);
        float2 b101 = __ldg(vol + B.r10 + B.x1);
        float2 b011 = __ldg(vol + B.r01 + B.x1);
        float2 b111 = __ldg(vol + B.r11 + B.x1);

        int rowA = (warp << 2) + jj * 2;

        float2 accA = lerp8(A, a000, a001, a010, a011, a100, a101, a110, a111);
        tx[rowA][lane] = accA.x;
        ty[rowA][lane] = accA.y;

        float2 accB = lerp8(B, b000, b001, b010, b011, b100, b101, b110, b111);
        tx[rowA + 1][lane] = accB.x;
        ty[rowA + 1][lane] = accB.y;
    }

    __syncthreads();

    size_t out_base = (((size_t)b << 7) + i0) << 14;
    #pragma unroll
    for (int j = 0; j < 4; j++) {
        int i1l = warp + (j << 3);
        float2 v;
        v.x = tx[lane][i1l];
        v.y = ty[lane][i1l];
        out[out_base + (size_t)(i1t + i1l) * 128 + (i2t + lane)] = v;
    }
}

extern "C" void kernel_launch(void* const* d_in, const int* in_sizes, int n_in,
                              void* d_out, int out_size)
{
    const float* images = (const float*)d_in[0];
    const float* params = (const float*)d_in[1];
    float2* out = (float2*)d_out;

    dim3 grid(16, 128, 4);   // (i2t,i1t) x i0 x b
    st3d_kernel<<<grid, 256>>>(images, params, out);
}

// round 9
// speedup vs baseline: 1.0801x; 1.0437x over previous
#include <cuda_runtime.h>

// SpatialTransformer3D: B=4, vol 128^3, C=2, resampled 128^3.
// R9 = ncu-best body (R7) without the constant-memcpy node, plus:
//  - corner/address computation split from weight computation: addresses
//    before the 16-load batch, weights after (covered by load latency)
//  - 32-bit byte offsets on a uniform base -> LDG [UR+R] addressing
// Tile 32(i1) x 32(i2); lanes along i1 (coalesced gathers), merged float2
// smem tile (64-bit transpose at the 2-phase floor), coalesced i2 stores.

#define R3_ (128*128*128)

__device__ __forceinline__ int clampi(int v, int lo, int hi) {
    return v < lo ? lo : (v > hi ? hi : v);
}

struct Pt {
    unsigned xb0, xb1;                   // x corner byte offsets (x<<3)
    unsigned rb00, rb01, rb10, rb11;     // row byte offsets (z<<17)+(y<<10)
    float x, y, z;
    int x0, x1, y0, y1, z0, z1;
};

__device__ __forceinline__ Pt make_pt(float x, float y, float z) {
    Pt p;
    int xi = (int)x, yi = (int)y, zi = (int)z;   // trunc toward zero (astype)
    p.x0 = clampi(xi,     0, 127);
    p.x1 = clampi(xi + 1, 0, 127);
    p.y0 = clampi(yi,     0, 127);
    p.y1 = clampi(yi + 1, 0, 127);
    p.z0 = clampi(zi,     0, 127);
    p.z1 = clampi(zi + 1, 0, 127);
    unsigned iz0 = (unsigned)p.z0 << 17, iz1 = (unsigned)p.z1 << 17;
    unsigned iy0 = (unsigned)p.y0 << 10, iy1 = (unsigned)p.y1 << 10;
    p.rb00 = iz0 + iy0;  p.rb01 = iz0 + iy1;
    p.rb10 = iz1 + iy0;  p.rb11 = iz1 + iy1;
    p.xb0 = (unsigned)p.x0 << 3;
    p.xb1 = (unsigned)p.x1 << 3;
    p.x = x; p.y = y; p.z = z;
    return p;
}

__device__ __forceinline__ float2 ld2(const char* base, unsigned off) {
    return __ldg((const float2*)(base + off));
}

// weights computed here (after loads were issued), then weighted sum
__device__ __forceinline__ float2 lerp8(const Pt& p,
    float2 v000, float2 v001, float2 v010, float2 v011,
    float2 v100, float2 v101, float2 v110, float2 v111)
{
    float wx0 = (float)p.x1 - p.x, wx1 = p.x - (float)p.x0;
    float wy0 = (float)p.y1 - p.y, wy1 = p.y - (float)p.y0;
    float wz0 = (float)p.z1 - p.z, wz1 = p.z - (float)p.z0;

    float wxy00 = wx0 * wy0;
    float wxy01 = wx0 * wy1;
    float wxy10 = wx1 * wy0;
    float wxy11 = wx1 * wy1;
    float w000 = wxy00 * wz0, w100 = wxy00 * wz1;
    float w010 = wxy01 * wz0, w110 = wxy01 * wz1;
    float w001 = wxy10 * wz0, w101 = wxy10 * wz1;
    float w011 = wxy11 * wz0, w111 = wxy11 * wz1;

    float2 acc;
    acc.x = w000 * v000.x;                 acc.y = w000 * v000.y;
    acc.x = fmaf(w100, v100.x, acc.x);     acc.y = fmaf(w100, v100.y, acc.y);
    acc.x = fmaf(w010, v010.x, acc.x);     acc.y = fmaf(w010, v010.y, acc.y);
    acc.x = fmaf(w110, v110.x, acc.x);     acc.y = fmaf(w110, v110.y, acc.y);
    acc.x = fmaf(w001, v001.x, acc.x);     acc.y = fmaf(w001, v001.y, acc.y);
    acc.x = fmaf(w101, v101.x, acc.x);     acc.y = fmaf(w101, v101.y, acc.y);
    acc.x = fmaf(w011, v011.x, acc.x);     acc.y = fmaf(w011, v011.y, acc.y);
    acc.x = fmaf(w111, v111.x, acc.x);     acc.y = fmaf(w111, v111.y, acc.y);
    return acc;
}

__global__ __launch_bounds__(256, 4)
void st3d_kernel(const float* __restrict__ images,
                 const float* __restrict__ params,
                 float2* __restrict__ out)
{
    __shared__ float2 tile[32][33];

    int lane = threadIdx.x & 31;
    int warp = threadIdx.x >> 5;

    int i2t = (blockIdx.x & 3) << 5;
    int i1t = (blockIdx.x >> 2) << 5;
    int i0  = blockIdx.y;
    int b   = blockIdx.z;

    const float* m = params + b * 12;
    float m00 = __ldg(m+0),  m01 = __ldg(m+1),  m02 = __ldg(m+2),  m03 = __ldg(m+3);
    float m10 = __ldg(m+4),  m11 = __ldg(m+5),  m12 = __ldg(m+6),  m13 = __ldg(m+7);
    float m20 = __ldg(m+8),  m21 = __ldg(m+9),  m22 = __ldg(m+10), m23 = __ldg(m+11);

    const float step = 2.0f / 127.0f;
    int i1 = i1t + lane;
    float xn = fmaf((float)i1, step, -1.0f);
    float yn = fmaf((float)i0, step, -1.0f);

    // coord(fi2) = d * fi2 + c
    float gx = fmaf(m00, xn, fmaf(m01, yn, m03));
    float gy = fmaf(m10, xn, fmaf(m11, yn, m13));
    float gz = fmaf(m20, xn, fmaf(m21, yn, m23));
    float dxz = 64.0f * step * m02;
    float dyz = 64.0f * step * m12;
    float dzz = 64.0f * step * m22;
    float cx = (gx - m02 + 1.0f) * 64.0f;
    float cy = (gy - m12 + 1.0f) * 64.0f;
    float cz = (gz - m22 + 1.0f) * 64.0f;

    const char* __restrict__ vol =
        (const char*)images + ((size_t)b * R3_ * 8);

    float fbase = (float)(i2t + (warp << 2));

    #pragma unroll
    for (int jj = 0; jj < 2; jj++) {
        float fA = fbase + (float)(jj * 2);
        float fB = fA + 1.0f;

        Pt A = make_pt(fmaf(dxz, fA, cx), fmaf(dyz, fA, cy), fmaf(dzz, fA, cz));
        Pt B = make_pt(fmaf(dxz, fB, cx), fmaf(dyz, fB, cy), fmaf(dzz, fB, cz));

        // all 16 gathers issued before any weight math / consumption
        float2 a000 = ld2(vol, A.rb00 + A.xb0);
        float2 a100 = ld2(vol, A.rb10 + A.xb0);
        float2 a010 = ld2(vol, A.rb01 + A.xb0);
        float2 a110 = ld2(vol, A.rb11 + A.xb0);
        float2 a001 = ld2(vol, A.rb00 + A.xb1);
        float2 a101 = ld2(vol, A.rb10 + A.xb1);
        float2 a011 = ld2(vol, A.rb01 + A.xb1);
        float2 a111 = ld2(vol, A.rb11 + A.xb1);

        float2 b000 = ld2(vol, B.rb00 + B.xb0);
        float2 b100 = ld2(vol, B.rb10 + B.xb0);
        float2 b010 = ld2(vol, B.rb01 + B.xb0);
        float2 b110 = ld2(vol, B.rb11 + B.xb0);
        float2 b001 = ld2(vol, B.rb00 + B.xb1);
        float2 b101 = ld2(vol, B.rb10 + B.xb1);
        float2 b011 = ld2(vol, B.rb01 + B.xb1);
        float2 b111 = ld2(vol, B.rb11 + B.xb1);

        int rowA = (warp << 2) + jj * 2;
        tile[rowA][lane] =
            lerp8(A, a000, a001, a010, a011, a100, a101, a110, a111);
        tile[rowA + 1][lane] =
            lerp8(B, b000, b001, b010, b011, b100, b101, b110, b111);
    }

    __syncthreads();

    size_t out_base = (((size_t)b << 7) + i0) << 14;
    #pragma unroll
    for (int j = 0; j < 4; j++) {
        int i1l = warp + (j << 3);
        float2 v = tile[lane][i1l];
        out[out_base + (size_t)(i1t + i1l) * 128 + (i2t + lane)] = v;
    }
}

extern "C" void kernel_launch(void* const* d_in, const int* in_sizes, int n_in,
                              void* d_out, int out_size)
{
    const float* images = (const float*)d_in[0];
    const float* params = (const float*)d_in[1];
    float2* out = (float2*)d_out;

    dim3 grid(16, 128, 4);   // (i2t,i1t) x i0 x b
    st3d_kernel<<<grid, 256>>>(images, params, out);
}